// round 5
// baseline (speedup 1.0000x reference)
#include <cuda_runtime.h>
#include <cuda_bf16.h>
#include <cstdint>
#include <math.h>

#define BH 16
#define LSEQ 2048
#define DH 64
#define OUT_ELE (LSEQ * DH * BH)
#define ATT_ELE ((size_t)BH * LSEQ * LSEQ)

__device__ __nv_bfloat16 g_Qh[BH * LSEQ * DH];
__device__ __nv_bfloat16 g_Ql[BH * LSEQ * DH];
__device__ __nv_bfloat16 g_Kh[BH * LSEQ * DH];
__device__ __nv_bfloat16 g_Kl[BH * LSEQ * DH];
__device__ __nv_bfloat16 g_Vth[BH * DH * LSEQ];
__device__ __nv_bfloat16 g_Vtl[BH * DH * LSEQ];

__device__ __forceinline__ uint32_t smem_u32(const void* p) {
    uint32_t a;
    asm("{ .reg .u64 t; cvta.to.shared.u64 t, %1; cvt.u32.u64 %0, t; }" : "=r"(a) : "l"(p));
    return a;
}
__device__ __forceinline__ void ldsm4(uint32_t* r, uint32_t addr) {
    asm volatile("ldmatrix.sync.aligned.m8n8.x4.shared.b16 {%0,%1,%2,%3}, [%4];"
                 : "=r"(r[0]), "=r"(r[1]), "=r"(r[2]), "=r"(r[3]) : "r"(addr));
}
__device__ __forceinline__ void mma16816(float* c, const uint32_t* a, uint32_t b0, uint32_t b1) {
    asm volatile("mma.sync.aligned.m16n8k16.row.col.f32.bf16.bf16.f32 "
                 "{%0,%1,%2,%3}, {%4,%5,%6,%7}, {%8,%9}, {%0,%1,%2,%3};"
                 : "+f"(c[0]), "+f"(c[1]), "+f"(c[2]), "+f"(c[3])
                 : "r"(a[0]), "r"(a[1]), "r"(a[2]), "r"(a[3]), "r"(b0), "r"(b1));
}
__device__ __forceinline__ void split2(float a, float b, uint32_t& hi, uint32_t& lo) {
    __nv_bfloat16 ah = __float2bfloat16(a), bh = __float2bfloat16(b);
    float al = a - __bfloat162float(ah);
    float bl = b - __bfloat162float(bh);
    __nv_bfloat162 H; H.x = ah; H.y = bh;
    __nv_bfloat162 L; L.x = __float2bfloat16(al); L.y = __float2bfloat16(bl);
    hi = *reinterpret_cast<uint32_t*>(&H);
    lo = *reinterpret_cast<uint32_t*>(&L);
}
__device__ __forceinline__ void cpasync16(uint32_t dst, const void* src) {
    asm volatile("cp.async.cg.shared.global [%0], [%1], 16;" :: "r"(dst), "l"(src));
}
#define CP_COMMIT() asm volatile("cp.async.commit_group;" ::: "memory")
#define CP_WAIT1()  asm volatile("cp.async.wait_group 1;" ::: "memory")
#define CP_WAIT0()  asm volatile("cp.async.wait_group 0;" ::: "memory")
__device__ __forceinline__ uint32_t prmt_hi(uint32_t a, uint32_t b) {
    uint32_t d;
    asm("prmt.b32 %0, %1, %2, 0x7632;" : "=r"(d) : "r"(a), "r"(b));
    return d;
}
__device__ __forceinline__ uint32_t cvt_bf16x2(float hi, float lo) {
    uint32_t d;
    asm("cvt.rn.bf16x2.f32 %0, %1, %2;" : "=r"(d) : "f"(hi), "f"(lo));
    return d;
}

// ---------------- Prepass ----------------
__global__ void prep_q(const float* __restrict__ q) {
    int idx = blockIdx.x * 256 + threadIdx.x;
    float4 x = ((const float4*)q)[idx];
    x.x *= 0.125f; x.y *= 0.125f; x.z *= 0.125f; x.w *= 0.125f;
    uint32_t h0, l0, h1, l1;
    split2(x.x, x.y, h0, l0);
    split2(x.z, x.w, h1, l1);
    ((uint2*)g_Qh)[idx] = make_uint2(h0, h1);
    ((uint2*)g_Ql)[idx] = make_uint2(l0, l1);
}
__global__ void prep_k(const float* __restrict__ k) {
    int idx = blockIdx.x * 256 + threadIdx.x;
    float4 x = ((const float4*)k)[idx];
    uint32_t h0, l0, h1, l1;
    split2(x.x, x.y, h0, l0);
    split2(x.z, x.w, h1, l1);
    ((uint2*)g_Kh)[idx] = make_uint2(h0, h1);
    ((uint2*)g_Kl)[idx] = make_uint2(l0, l1);
}
__global__ void prep_v(const float* __restrict__ v) {
    __shared__ float vs[128 * 65];
    const int b = blockIdx.x >> 4, st = blockIdx.x & 15, tid = threadIdx.x;
    const float4* vp = (const float4*)(v + ((size_t)(b * LSEQ + st * 128)) * DH);
#pragma unroll
    for (int it = 0; it < 8; ++it) {
        int fi = it * 256 + tid;
        int s = fi >> 4, d4 = fi & 15;
        float4 x = vp[fi];
        vs[s * 65 + d4 * 4 + 0] = x.x;
        vs[s * 65 + d4 * 4 + 1] = x.y;
        vs[s * 65 + d4 * 4 + 2] = x.z;
        vs[s * 65 + d4 * 4 + 3] = x.w;
    }
    __syncthreads();
#pragma unroll
    for (int it = 0; it < 4; ++it) {
        int fo = it * 256 + tid;
        int d = fo >> 4, cu = fo & 15;
        float vv[8];
#pragma unroll
        for (int j = 0; j < 8; ++j) vv[j] = vs[(cu * 8 + j) * 65 + d];
        uint32_t hw[4], lw[4];
#pragma unroll
        for (int j = 0; j < 4; ++j) split2(vv[2 * j], vv[2 * j + 1], hw[j], lw[j]);
        size_t o = ((size_t)(b * DH + d)) * LSEQ + st * 128 + cu * 8;
        *(uint4*)(g_Vth + o) = make_uint4(hw[0], hw[1], hw[2], hw[3]);
        *(uint4*)(g_Vtl + o) = make_uint4(lw[0], lw[1], lw[2], lw[3]);
    }
}

// ---------------- Fused attention (512 threads, 16 warps) ----------------
#define SQH 0
#define SQL 16384
#define SB0 32768
#define SB1 65536
#define SB2 98304
#define SB3 131072
#define SRED 163840   /* 2KB: [row][wn] float2 */
#define SLZ  165888   /* 512B */
#define SMEM_TOT 166400

__global__ void __launch_bounds__(512, 1)
sdpa_fused(float* __restrict__ attn, float* __restrict__ lattn, float* __restrict__ outp) {
    extern __shared__ char sm[];
    const uint32_t sb = smem_u32(sm);
    const int tid = threadIdx.x, lane = tid & 31, w = tid >> 5;
    const int wm = w >> 1, wn = w & 1;          // 8 row-groups x 2 col-halves
    const int b = blockIdx.y, qbase = blockIdx.x * 128;

    const int arow = lane & 15, achk = lane >> 4;
    const int brow = ((lane >> 4) << 3) + (lane & 7), bch = (lane >> 3) & 1;
    const int qrow = wm * 16 + arow;            // A-fragment smem row (fixed)

    const char* kh_base = (const char*)(g_Kh + (size_t)b * LSEQ * DH);
    const char* kl_base = (const char*)(g_Kl + (size_t)b * LSEQ * DH);
    const char* vh_base = (const char*)(g_Vth + (size_t)b * DH * LSEQ);
    const char* vl_base = (const char*)(g_Vtl + (size_t)b * DH * LSEQ);

#define LOAD_K(buf, t) do {                                                    \
        const char* _sh = kh_base + (size_t)(t) * 16384;                       \
        const char* _sl = kl_base + (size_t)(t) * 16384;                       \
        _Pragma("unroll")                                                      \
        for (int r = 0; r < 2; ++r) {                                          \
            int fo = r * 512 + tid;                                            \
            int row = fo >> 3, cu = fo & 7;                                    \
            uint32_t off = (uint32_t)row * 128 + ((cu ^ (row & 7)) << 4);      \
            cpasync16(sb + (buf) + off, _sh + fo * 16);                        \
            cpasync16(sb + (buf) + 16384 + off, _sl + fo * 16);                \
        }                                                                      \
    } while (0)

#define LOAD_V(buf, t) do {                                                    \
        const char* _sh = vh_base + (size_t)(t) * 256;                         \
        const char* _sl = vl_base + (size_t)(t) * 256;                         \
        _Pragma("unroll")                                                      \
        for (int r = 0; r < 2; ++r) {                                          \
            int fo = r * 512 + tid;                                            \
            int row = fo >> 4, cu = fo & 15;                                   \
            uint32_t off = (uint32_t)row * 256 + ((cu ^ (row & 15)) << 4);     \
            size_t sof = (size_t)row * (LSEQ * 2) + cu * 16;                   \
            cpasync16(sb + (buf) + off, _sh + sof);                            \
            cpasync16(sb + (buf) + 16384 + off, _sl + sof);                    \
        }                                                                      \
    } while (0)

    // prologue: Q tile + K tile 0
    {
        const char* qh = (const char*)(g_Qh + (size_t)(b * LSEQ + qbase) * DH);
        const char* ql = (const char*)(g_Ql + (size_t)(b * LSEQ + qbase) * DH);
#pragma unroll
        for (int r = 0; r < 2; ++r) {
            int fo = r * 512 + tid;
            int row = fo >> 3, cu = fo & 7;
            uint32_t off = (uint32_t)row * 128 + ((cu ^ (row & 7)) << 4);
            cpasync16(sb + SQH + off, qh + fo * 16);
            cpasync16(sb + SQL + off, ql + fo * 16);
        }
        LOAD_K(SB0, 0);
        CP_COMMIT();
    }

    // QK for this warp's 16 rows x 64 cols (reloads Q frags from smem each tile)
#define COMPUTE_QK(c, kb) do {                                                 \
        _Pragma("unroll")                                                      \
        for (int nt = 0; nt < 8; ++nt) {                                       \
            c[nt][0] = 0.f; c[nt][1] = 0.f; c[nt][2] = 0.f; c[nt][3] = 0.f;    \
        }                                                                      \
        _Pragma("unroll")                                                      \
        for (int ks = 0; ks < 4; ++ks) {                                       \
            uint32_t aQh[4], aQl[4];                                           \
            uint32_t qad = sb + qrow * 128 +                                   \
                           (((ks * 2 + achk) ^ (qrow & 7)) << 4);              \
            ldsm4(aQh, qad);                                                   \
            ldsm4(aQl, qad + 16384);                                           \
            _Pragma("unroll")                                                  \
            for (int p = 0; p < 4; ++p) {                                      \
                int row = wn * 64 + p * 16 + brow;                             \
                uint32_t ad = sb + (kb) + row * 128 +                          \
                              (((ks * 2 + bch) ^ (row & 7)) << 4);             \
                uint32_t bh_[4], bl_[4];                                       \
                ldsm4(bh_, ad);                                                \
                ldsm4(bl_, ad + 16384);                                        \
                mma16816(c[2 * p],     aQh, bh_[0], bh_[1]);                   \
                mma16816(c[2 * p + 1], aQh, bh_[2], bh_[3]);                   \
                mma16816(c[2 * p],     aQh, bl_[0], bl_[1]);                   \
                mma16816(c[2 * p + 1], aQh, bl_[2], bl_[3]);                   \
                mma16816(c[2 * p],     aQl, bh_[0], bh_[1]);                   \
                mma16816(c[2 * p + 1], aQl, bh_[2], bh_[3]);                   \
            }                                                                  \
        }                                                                      \
    } while (0)

    float mrun[2] = {-INFINITY, -INFINITY}, lrun[2] = {0.f, 0.f};

    // ================= Sweep 1: stats =================
    for (int t = 0; t < 16; ++t) {
        if (t < 15) {
            LOAD_K((((t + 1) & 1) ? SB1 : SB0), t + 1);
            CP_COMMIT();
            CP_WAIT1();
        } else {
            CP_WAIT0();
        }
        __syncthreads();
        float c[8][4];
        COMPUTE_QK(c, ((t & 1) ? SB1 : SB0));
#pragma unroll
        for (int h = 0; h < 2; ++h) {
            float mx = mrun[h];
#pragma unroll
            for (int nt = 0; nt < 8; ++nt)
                mx = fmaxf(mx, fmaxf(c[nt][2 * h], c[nt][2 * h + 1]));
            float sum = 0.f;
#pragma unroll
            for (int nt = 0; nt < 8; ++nt)
                sum += __expf(c[nt][2 * h] - mx) + __expf(c[nt][2 * h + 1] - mx);
            lrun[h] = lrun[h] * __expf(mrun[h] - mx) + sum;
            mrun[h] = mx;
        }
        __syncthreads();
    }

    // reduce lane quads, then combine the two column halves per row
#pragma unroll
    for (int h = 0; h < 2; ++h) {
        float m = mrun[h], l = lrun[h];
#pragma unroll
        for (int o = 1; o <= 2; o <<= 1) {
            float om = __shfl_xor_sync(0xffffffffu, m, o);
            float ol = __shfl_xor_sync(0xffffffffu, l, o);
            float nm = fmaxf(m, om);
            l = l * __expf(m - nm) + ol * __expf(om - nm);
            m = nm;
        }
        if ((lane & 3) == 0) {
            int row = wm * 16 + (lane >> 2) + 8 * h;
            *(float2*)(sm + SRED + (row * 2 + wn) * 8) = make_float2(m, l);
        }
    }
    __syncthreads();
    float* lzs = (float*)(sm + SLZ);
    if (tid < 128) {
        float2 a = *(float2*)(sm + SRED + (tid * 2) * 8);
        float2 cc = *(float2*)(sm + SRED + (tid * 2 + 1) * 8);
        float m = fmaxf(a.x, cc.x);
        float l = a.y * __expf(a.x - m) + cc.y * __expf(cc.x - m);
        lzs[tid] = m + logf(l);
    }
    __syncthreads();
    const float lz0 = lzs[wm * 16 + (lane >> 2)];
    const float lz1 = lzs[wm * 16 + (lane >> 2) + 8];

    // ================= Sweep 2: emit + PV (k-split across wn) =================
    float o[8][4];
#pragma unroll
    for (int g = 0; g < 8; ++g)
#pragma unroll
        for (int j = 0; j < 4; ++j) o[g][j] = 0.f;

    LOAD_K(SB0, 0);
    LOAD_V(SB2, 0);
    CP_COMMIT();

    float* aRow = attn + ((size_t)(b * LSEQ + qbase + wm * 16 + (lane >> 2))) * LSEQ +
                  wn * 64 + (lane & 3) * 2;
    float* lRow = lattn + ((size_t)(b * LSEQ + qbase + wm * 16 + (lane >> 2))) * LSEQ +
                  wn * 64 + (lane & 3) * 2;

    for (int t = 0; t < 16; ++t) {
        if (t < 15) {
            LOAD_K((((t + 1) & 1) ? SB1 : SB0), t + 1);
            LOAD_V((((t + 1) & 1) ? SB3 : SB2), t + 1);
            CP_COMMIT();
            CP_WAIT1();
        } else {
            CP_WAIT0();
        }
        __syncthreads();

        float c[8][4];
        COMPUTE_QK(c, ((t & 1) ? SB1 : SB0));

        // S -> attn/lattn stores + register-resident P fragments (warp's 64 kcols)
        uint32_t aPh[4][4], aPl[4][4];
        float* aT = aRow + t * 128;
        float* lT = lRow + t * 128;
#pragma unroll
        for (int kc = 0; kc < 4; ++kc) {
#pragma unroll
            for (int qq = 0; qq < 2; ++qq) {
                const int nt = 2 * kc + qq;
                float la0 = c[nt][0] - lz0, la1 = c[nt][1] - lz0;
                float la2 = c[nt][2] - lz1, la3 = c[nt][3] - lz1;
                float p0 = __expf(la0), p1 = __expf(la1);
                float p2 = __expf(la2), p3 = __expf(la3);
                *(float2*)(aT + nt * 8) = make_float2(p0, p1);
                *(float2*)(aT + 8 * LSEQ + nt * 8) = make_float2(p2, p3);
                *(float2*)(lT + nt * 8) = make_float2(la0, la1);
                *(float2*)(lT + 8 * LSEQ + nt * 8) = make_float2(la2, la3);
                uint32_t u0 = __float_as_uint(p0), u1 = __float_as_uint(p1);
                uint32_t u2 = __float_as_uint(p2), u3 = __float_as_uint(p3);
                aPh[kc][qq * 2 + 0] = prmt_hi(u0, u1);
                aPh[kc][qq * 2 + 1] = prmt_hi(u2, u3);
                aPl[kc][qq * 2 + 0] = cvt_bf16x2(p1 - __uint_as_float(u1 & 0xFFFF0000u),
                                                 p0 - __uint_as_float(u0 & 0xFFFF0000u));
                aPl[kc][qq * 2 + 1] = cvt_bf16x2(p3 - __uint_as_float(u3 & 0xFFFF0000u),
                                                 p2 - __uint_as_float(u2 & 0xFFFF0000u));
            }
        }

        // PV partial over this warp's 64 kcols: O += Ph*Vh + Ph*Vl + Pl*Vh
        const uint32_t vb = sb + ((t & 1) ? SB3 : SB2);
#pragma unroll
        for (int kc = 0; kc < 4; ++kc) {
#pragma unroll
            for (int g2 = 0; g2 < 4; ++g2) {
                int row = g2 * 16 + brow;   // d-rows 0..63
                uint32_t ad = vb + row * 256 +
                              (((wn * 8 + kc * 2 + bch) ^ (row & 15)) << 4);
                uint32_t vh_[4], vl_[4];
                ldsm4(vh_, ad);
                ldsm4(vl_, ad + 16384);
                mma16816(o[2 * g2],     aPh[kc], vh_[0], vh_[1]);
                mma16816(o[2 * g2 + 1], aPh[kc], vh_[2], vh_[3]);
                mma16816(o[2 * g2],     aPh[kc], vl_[0], vl_[1]);
                mma16816(o[2 * g2 + 1], aPh[kc], vl_[2], vl_[3]);
                mma16816(o[2 * g2],     aPl[kc], vh_[0], vh_[1]);
                mma16816(o[2 * g2 + 1], aPl[kc], vh_[2], vh_[3]);
            }
        }
        __syncthreads();
    }

    // ---- epilogue: reduce wn partials via smem, write head-folded output ----
    float* ored = (float*)sm;   // 128 x 64 fp32 = 32KB (Q smem dead)
    if (wn == 1) {
#pragma unroll
        for (int nt = 0; nt < 8; ++nt) {
            int col = nt * 8 + (lane & 3) * 2;
            *(float2*)(ored + (wm * 16 + (lane >> 2)) * 64 + col) = make_float2(o[nt][0], o[nt][1]);
            *(float2*)(ored + (wm * 16 + (lane >> 2) + 8) * 64 + col) = make_float2(o[nt][2], o[nt][3]);
        }
    }
    __syncthreads();
    if (wn == 0) {
        int qr = qbase + wm * 16 + (lane >> 2);
        float* dp = outp + (size_t)qr * (DH * BH) + b * DH + (lane & 3) * 2;
#pragma unroll
        for (int nt = 0; nt < 8; ++nt) {
            int col = nt * 8 + (lane & 3) * 2;
            float2 r0 = *(float2*)(ored + (wm * 16 + (lane >> 2)) * 64 + col);
            float2 r1 = *(float2*)(ored + (wm * 16 + (lane >> 2) + 8) * 64 + col);
            *(float2*)(dp + nt * 8) = make_float2(o[nt][0] + r0.x, o[nt][1] + r0.y);
            *(float2*)(dp + 8 * (DH * BH) + nt * 8) = make_float2(o[nt][2] + r1.x, o[nt][3] + r1.y);
        }
    }
}

extern "C" void kernel_launch(void* const* d_in, const int* in_sizes, int n_in,
                              void* d_out, int out_size) {
    const float* q = (const float*)d_in[0];
    const float* k = (const float*)d_in[1];
    const float* v = (const float*)d_in[2];

    float* outp = (float*)d_out;
    float* attn = outp + OUT_ELE;
    float* lattn = attn + ATT_ELE;

    cudaFuncSetAttribute(sdpa_fused, cudaFuncAttributeMaxDynamicSharedMemorySize, SMEM_TOT);

    prep_q<<<2048, 256>>>(q);
    prep_k<<<2048, 256>>>(k);
    prep_v<<<256, 256>>>(v);

    dim3 grid(LSEQ / 128, BH);
    sdpa_fused<<<grid, 512, SMEM_TOT>>>(attn, lattn, outp);
}